// round 11
// baseline (speedup 1.0000x reference)
#include <cuda_runtime.h>
#include <stdint.h>
#include <math.h>

#define BS   8
#define CCH  256
#define NND  9216     // H*W
#define EED  9215     // N-1 edges
#define EEDP 9216     // padded
#define ZETA 0.01f

#define CPB  16               // channels per dist block
#define GQ   (CCH/CPB)        // 16 groups per batch
#define TCH  2                // channels per tile step
#define NSTEP (CPB/TCH)       // 8 tile steps
#define MAXD 511
#define NT   1024
#define EPT  9                // ceil(EED/NT)
#define NCHUNK (NND/NT)       // 9
#define GRID1 (BS*GQ + BS)    // 128 dist + 8 prologue = 136

// static device scratch (zero-init at load; flags/g_sum self-resetting)
__device__ float g_sum[(size_t)BS * EED];        // per-edge squared dist
__device__ int   g_T[(size_t)BS * EEDP];         // child id, parent-CSR order
__device__ int   g_rowPtr[BS][NND + 1];          // CSR row pointers
__device__ int   g_pList[(size_t)BS * NND];      // parents sorted by level
__device__ int   g_pLvlo[BS][MAXD + 2];          // per-level segment offsets
__device__ int2  g_meta[BS];                     // (maxLvl, bad)
__device__ float g_Z[(size_t)BS * NND];          // G field (denominator)
__device__ int   g_flagW[BS];                    // F-block done reading g_sum
__device__ int   g_flagZ[BS];                    // Z published

extern __shared__ float dyn_smem[];

__device__ __forceinline__ void cp_async16(uint32_t saddr, const void* gptr) {
    asm volatile("cp.async.cg.shared.global [%0], [%1], 16;\n"
                 :: "r"(saddr), "l"(gptr));
}
__device__ __forceinline__ void cp_commit() {
    asm volatile("cp.async.commit_group;\n");
}
template <int N>
__device__ __forceinline__ void cp_wait() {
    asm volatile("cp.async.wait_group %0;\n" :: "n"(N));
}

// ---------------------------------------------------------------------------
// Dist role (unchanged): double-buffered cp.async; REDG into g_sum.
// ---------------------------------------------------------------------------
__device__ void dist_role(const float* __restrict__ emb,
                          const int*   __restrict__ tree, int id) {
    float* buf0 = dyn_smem;
    float* buf1 = dyn_smem + TCH * NND;
    const int b   = id / GQ;
    const int g   = id % GQ;
    const int tid = threadIdx.x;

    const float* base = emb + ((size_t)b * CCH + (size_t)g * CPB) * NND;
    uint32_t s0 = (uint32_t)__cvta_generic_to_shared(buf0);
    uint32_t s1 = (uint32_t)__cvta_generic_to_shared(buf1);
    const int WORDS = TCH * NND / 4;

    for (int i = tid; i < WORDS; i += NT)
        cp_async16(s0 + i * 16, base + i * 4);
    cp_commit();

    const int2* tr2 = (const int2*)(tree + (size_t)b * EED * 2);
    int2 ed[EPT];
    float acc[EPT];
#pragma unroll
    for (int k = 0; k < EPT; k++) {
        int e = tid + k * NT;
        ed[k]  = (e < EED) ? tr2[e] : make_int2(0, 0);
        acc[k] = 0.f;
    }

    for (int t = 0; t < NSTEP; t++) {
        if (t + 1 < NSTEP) {
            uint32_t dst = (t & 1) ? s0 : s1;
            const float* srcp = base + (size_t)(t + 1) * TCH * NND;
            for (int i = tid; i < WORDS; i += NT)
                cp_async16(dst + i * 16, srcp + i * 4);
            cp_commit();
            cp_wait<1>();
        } else {
            cp_wait<0>();
        }
        __syncthreads();
        const float* cur = (t & 1) ? buf1 : buf0;
#pragma unroll
        for (int k = 0; k < EPT; k++) {
            float a0 = cur[ed[k].x];
            float b0 = cur[ed[k].y];
            float a1 = cur[NND + ed[k].x];
            float b1 = cur[NND + ed[k].y];
            float d0 = a0 - b0, d1 = a1 - b1;
            acc[k] += d0 * d0 + d1 * d1;
        }
        __syncthreads();
    }

    float* sp = g_sum + (size_t)b * EED;
#pragma unroll
    for (int k = 0; k < EPT; k++) {
        int e = tid + k * NT;
        if (e < EED) atomicAdd(sp + e, acc[k]);
    }
}

// ---------------------------------------------------------------------------
// Prologue role: tree-only, overlapped with dist. Builds parent-CSR
// (rowPtr + child array) and a depth-sorted parent list with per-level
// segment offsets. smem: par | dep | cnt | cur (4 x 9216 ints = 147456 B).
// ---------------------------------------------------------------------------
__device__ void prologue_role(const int* __restrict__ tree, int b) {
    const int tid = threadIdx.x;
    const int wid = tid >> 5;
    const int lid = tid & 31;

    int* par = (int*)dyn_smem;
    int* dep = par + NND;
    int* cnt = dep + NND;
    int* cur = cnt + NND;

    __shared__ int histP[MAXD + 1];
    __shared__ int pLvlo[MAXD + 2];
    __shared__ int warpsum[32];
    __shared__ int s_maxLvl, s_bad;

    const int2* tr2 = (const int2*)(tree + (size_t)b * EED * 2);

    if (tid == 0) { s_maxLvl = 1; s_bad = 0; par[0] = 0; dep[0] = 0; }
    for (int i = tid; i < NND; i += NT) cnt[i] = 0;
    int2 ed[EPT];
#pragma unroll
    for (int k = 0; k < EPT; k++) {
        int e = tid + k * NT;
        ed[k] = (e < EED) ? tr2[e] : make_int2(0, 0);
        if (e < EED) par[ed[k].y] = ed[k].x;
    }
    __syncthreads();
#pragma unroll
    for (int k = 0; k < EPT; k++) {
        int e = tid + k * NT;
        if (e < EED) atomicAdd(&cnt[ed[k].x], 1);
    }

    // ---- depth: chunked walk (parent index < child index) ----
#pragma unroll 1
    for (int c = 0; c < NCHUNK; c++) {
        int i = c * NT + tid;
        if (i > 0) {
            int B = c * NT;
            int j = par[i], d = 1;
            while (j >= B && j > 0) { j = par[j]; d++; }
            dep[i] = d + dep[j];
        }
        __syncthreads();
    }

    // ---- segment histogram: per child-level, # parents with children ----
    for (int k = tid; k <= MAXD; k += NT) histP[k] = 0;
    __syncthreads();
    for (int i = tid; i < NND; i += NT) {
        if (cnt[i] > 0) {
            int l = dep[i] + 1; l = l > MAXD ? MAXD : l;
            atomicAdd(&histP[l], 1);
        }
    }
    __syncthreads();

    // ---- 512-bin scan of histP -> pLvlo (+ cursor in histP) ----
    {
        int binv = 0, incl = 0, bin = 0;
        if (wid < 16) {
            bin  = wid * 32 + lid;
            binv = histP[bin];
            int v = binv;
#pragma unroll
            for (int off = 1; off < 32; off <<= 1) {
                int t = __shfl_up_sync(0xffffffffu, v, off);
                if (lid >= off) v += t;
            }
            if (lid == 31) warpsum[wid] = v;
            incl = v;
        }
        __syncthreads();
        if (wid == 0 && lid < 16) {
            int v = warpsum[lid];
#pragma unroll
            for (int off = 1; off < 16; off <<= 1) {
                int t = __shfl_up_sync(0xffffu, v, off);
                if (lid >= off) v += t;
            }
            warpsum[lid] = v;
        }
        __syncthreads();
        if (wid < 16) {
            incl += wid ? warpsum[wid - 1] : 0;
            pLvlo[bin + 1] = incl;
            histP[bin] = incl - binv;        // exclusive cursor
            if (binv > 0)  atomicMax(&s_maxLvl, bin);
            if (binv > 32) atomicMax(&s_bad, bin);
        }
        if (tid == 0) pLvlo[0] = 0;
        __syncthreads();
    }

    // ---- rowPtr: 9216-wide exclusive scan of cnt (carry across chunks) ----
    int carry = 0;
#pragma unroll 1
    for (int c = 0; c < NCHUNK; c++) {
        int i = c * NT + tid;
        int v = cnt[i];
        int incl = v;
#pragma unroll
        for (int off = 1; off < 32; off <<= 1) {
            int t = __shfl_up_sync(0xffffffffu, incl, off);
            if (lid >= off) incl += t;
        }
        if (lid == 31) warpsum[wid] = incl;
        __syncthreads();
        if (wid == 0) {
            int vv = warpsum[lid];
#pragma unroll
            for (int off = 1; off < 32; off <<= 1) {
                int t = __shfl_up_sync(0xffffffffu, vv, off);
                if (lid >= off) vv += t;
            }
            warpsum[lid] = vv;
        }
        __syncthreads();
        int excl = incl - v + (wid ? warpsum[wid - 1] : 0) + carry;
        cur[i] = excl;
        g_rowPtr[b][i] = excl;
        carry += warpsum[31];
        __syncthreads();
    }
    if (tid == 0) g_rowPtr[b][NND] = EED;

    // ---- parent scatter: pList ordered by child level ----
    for (int i = tid; i < NND; i += NT) {
        if (cnt[i] > 0) {
            int l = dep[i] + 1; l = l > MAXD ? MAXD : l;
            int sidx = atomicAdd(&histP[l], 1);
            g_pList[(size_t)b * NND + sidx] = i;
        }
    }

    // ---- edge scatter into parent-CSR order ----
#pragma unroll
    for (int k = 0; k < EPT; k++) {
        int e = tid + k * NT;
        if (e < EED) {
            int pos = atomicAdd(&cur[ed[k].x], 1);
            g_T[(size_t)b * EEDP + pos] = ed[k].y;
        }
    }

    for (int k = tid; k <= MAXD + 1; k += NT) g_pLvlo[b][k] = pLvlo[k];
    __syncthreads();
    if (tid == 0) g_meta[b] = make_int2(s_maxLvl, s_bad);
}

__global__ void __launch_bounds__(NT, 1)
fused_kernel(const float* __restrict__ emb, const int* __restrict__ tree) {
    if (blockIdx.x < BS * GQ) dist_role(emb, tree, blockIdx.x);
    else                      prologue_role(tree, blockIdx.x - BS * GQ);
}

// ---------------------------------------------------------------------------
// Pass kernel: 16 blocks = (batch, field), 1024 threads. Segment-parallel:
// one thread per parent segment -> no smem atomics. 2-tier sync (R8 shape):
// levels with <=32 segments on warp 0 (provably all levels beyond `bad`).
// Field 0 = F (final divide), field 1 = G (publishes Z, re-zeroes g_sum).
// smem: S f[NND] | T i[EEDP] | W f[EEDP] | PL i[NND] | RP i[NND+1]
// ---------------------------------------------------------------------------
__global__ void __launch_bounds__(NT, 1)
pass_kernel(const float* __restrict__ fin, float* __restrict__ out) {
    const int b     = blockIdx.x >> 1;
    const int which = blockIdx.x & 1;
    const int tid   = threadIdx.x;
    const int wid   = tid >> 5;
    const int lid   = tid & 31;

    char*  smbase = (char*)dyn_smem;
    float* S  = (float*)smbase;
    int*   T  = (int*)(smbase + (size_t)NND * 4);
    float* W  = (float*)(smbase + (size_t)NND * 4 + (size_t)EEDP * 4);
    int*   PL = (int*)(smbase + (size_t)NND * 4 + (size_t)EEDP * 8);
    int*   RP = (int*)(smbase + (size_t)NND * 8 + (size_t)EEDP * 8);

    __shared__ int pLvlo[MAXD + 2];

    const int2 meta = g_meta[b];
    const int maxLvl = meta.x, bad = meta.y;

    for (int k = tid; k <= maxLvl + 1; k += NT) pLvlo[k] = g_pLvlo[b][k];

    // load CSR child array + weights (edge id = child - 1)
    const int*   gT = g_T + (size_t)b * EEDP;
    float*       sp = g_sum + (size_t)b * EED;
    for (int i = tid; i < EED; i += NT) {
        int t = gT[i];
        T[i] = t;
        W[i] = __expf(-ZETA * __ldg((const float*)sp + (t - 1)));
    }
    for (int i = tid; i < NND; i += NT) PL[i] = g_pList[(size_t)b * NND + i];
    for (int i = tid; i <= NND; i += NT) RP[i] = g_rowPtr[b][i];

    // init field
    if (which == 0) {
        const float* fb = fin + (size_t)b * NND;
        for (int i = tid; i < NND; i += NT) S[i] = fb[i];
    } else {
        for (int i = tid; i < NND; i += NT) S[i] = 1.f;
    }
    __syncthreads();

    // F-block signals it is done reading g_sum
    if (which == 0 && tid == 0) {
        __threadfence();
        atomicExch(&g_flagW[b], 1);
    }

    // ---- UP pass: tail (deep, <=32 segments/level) on warp 0 first ----
    if (wid == 0) {
#pragma unroll 1
        for (int d = maxLvl; d > bad; --d) {
            int j = pLvlo[d] + lid;
            if (j < pLvlo[d + 1]) {
                int p = PL[j];
                int k0 = RP[p], k1 = RP[p + 1];
                float acc = 0.f;
                for (int k = k0; k < k1; k++) acc += W[k] * S[T[k]];
                S[p] += acc;
            }
            __syncwarp();
        }
    }
    __syncthreads();
#pragma unroll 1
    for (int d = bad; d >= 1; --d) {
        int end = pLvlo[d + 1];
        for (int j = pLvlo[d] + tid; j < end; j += NT) {
            int p = PL[j];
            int k0 = RP[p], k1 = RP[p + 1];
            float acc = 0.f;
            for (int k = k0; k < k1; k++) acc += W[k] * S[T[k]];
            S[p] += acc;
        }
        __syncthreads();
    }

    // ---- DOWN pass ----
#pragma unroll 1
    for (int d = 1; d <= bad; ++d) {
        int end = pLvlo[d + 1];
        for (int j = pLvlo[d] + tid; j < end; j += NT) {
            int p = PL[j];
            int k0 = RP[p], k1 = RP[p + 1];
            float ps = S[p];
            for (int k = k0; k < k1; k++) {
                int t = T[k];
                float w = W[k];
                S[t] = w * ps + (1.f - w * w) * S[t];
            }
        }
        __syncthreads();
    }
    if (wid == 0) {
#pragma unroll 1
        for (int d = bad + 1; d <= maxLvl; ++d) {
            int j = pLvlo[d] + lid;
            if (j < pLvlo[d + 1]) {
                int p = PL[j];
                int k0 = RP[p], k1 = RP[p + 1];
                float ps = S[p];
                for (int k = k0; k < k1; k++) {
                    int t = T[k];
                    float w = W[k];
                    S[t] = w * ps + (1.f - w * w) * S[t];
                }
            }
            __syncwarp();
        }
    }
    __syncthreads();

    if (which == 1) {
        // publish Z, then (after F-block released g_sum) re-zero it
        float* zp = g_Z + (size_t)b * NND;
        for (int i = tid; i < NND; i += NT) zp[i] = S[i];
        __threadfence();
        __syncthreads();
        if (tid == 0) {
            atomicExch(&g_flagZ[b], 1);
            while (atomicAdd(&g_flagW[b], 0) == 0) __nanosleep(64);
            atomicExch(&g_flagW[b], 0);        // reset for next replay
        }
        __syncthreads();
        for (int e = tid; e < EED; e += NT) sp[e] = 0.f;
    } else {
        // wait for Z, divide, write output
        if (tid == 0) {
            while (atomicAdd(&g_flagZ[b], 0) == 0) __nanosleep(64);
            __threadfence();
            atomicExch(&g_flagZ[b], 0);        // reset for next replay
        }
        __syncthreads();
        const float* zp = g_Z + (size_t)b * NND;
        float* ob = out + (size_t)b * NND;
        for (int i = tid; i < NND; i += NT) ob[i] = S[i] / zp[i];
    }
}

// ---------------------------------------------------------------------------
extern "C" void kernel_launch(void* const* d_in, const int* in_sizes, int n_in,
                              void* d_out, int out_size) {
    const float* f    = (const float*)d_in[0];   // feature_in [8,1,96,96]
    const float* emb  = (const float*)d_in[1];   // embed_in   [8,256,96,96]
    const int*   tree = (const int*)d_in[2];     // tree       [8,9215,2]
    float*       out  = (float*)d_out;           // [8,1,96,96]

    size_t smem1 = 2 * (size_t)TCH * NND * sizeof(float);   // 147456 B
    cudaFuncSetAttribute(fused_kernel,
                         cudaFuncAttributeMaxDynamicSharedMemorySize,
                         (int)smem1);
    fused_kernel<<<GRID1, NT, smem1>>>(emb, tree);

    size_t smem2 = (size_t)NND * 8 + (size_t)EEDP * 8 + ((size_t)NND + 1) * 4;
    cudaFuncSetAttribute(pass_kernel,
                         cudaFuncAttributeMaxDynamicSharedMemorySize,
                         (int)smem2);
    pass_kernel<<<2 * BS, NT, smem2>>>(f, out);
}

// round 12
// speedup vs baseline: 1.1511x; 1.1511x over previous
#include <cuda_runtime.h>
#include <stdint.h>
#include <math.h>

#define BS   8
#define CCH  256
#define NND  9216     // H*W
#define EED  9215     // N-1 edges
#define EEDP 9216     // padded
#define ZETA 0.01f

#define CPB  16               // channels per dist block
#define GQ   (CCH/CPB)        // 16 groups per batch
#define TCH  2                // channels per tile step
#define NSTEP (CPB/TCH)       // 8 tile steps
#define MAXD 511
#define NT   1024
#define EPT  9                // ceil(EED/NT)
#define NCHUNK (NND/NT)       // 9
#define GRID1 (BS*GQ + BS)    // 128 dist + 8 prologue = 136

// static device scratch (zero-init at load; flags/g_sum self-resetting)
__device__ float g_sum[(size_t)BS * EED];        // per-edge squared dist
__device__ int2  g_ST[(size_t)BS * EEDP];        // level-sorted (s,t)
__device__ int   g_lvlo[BS][MAXD + 2];
__device__ int2  g_meta[BS];                     // (maxLvl, bad)
__device__ float g_Z[(size_t)BS * NND];          // G field (denominator)
__device__ int   g_flagW[BS];                    // F-block done reading g_sum
__device__ int   g_flagZ[BS];                    // Z published

extern __shared__ float dyn_smem[];

__device__ __forceinline__ void cp_async16(uint32_t saddr, const void* gptr) {
    asm volatile("cp.async.cg.shared.global [%0], [%1], 16;\n"
                 :: "r"(saddr), "l"(gptr));
}
__device__ __forceinline__ void cp_commit() {
    asm volatile("cp.async.commit_group;\n");
}
template <int N>
__device__ __forceinline__ void cp_wait() {
    asm volatile("cp.async.wait_group %0;\n" :: "n"(N));
}

// ---------------------------------------------------------------------------
// Dist role: one block per (batch, 16-channel group); double-buffered
// cp.async tiles; per-edge partials reduced into g_sum via REDG atomics.
// ---------------------------------------------------------------------------
__device__ void dist_role(const float* __restrict__ emb,
                          const int*   __restrict__ tree, int id) {
    float* buf0 = dyn_smem;
    float* buf1 = dyn_smem + TCH * NND;
    const int b   = id / GQ;
    const int g   = id % GQ;
    const int tid = threadIdx.x;

    const float* base = emb + ((size_t)b * CCH + (size_t)g * CPB) * NND;
    uint32_t s0 = (uint32_t)__cvta_generic_to_shared(buf0);
    uint32_t s1 = (uint32_t)__cvta_generic_to_shared(buf1);
    const int WORDS = TCH * NND / 4;

    for (int i = tid; i < WORDS; i += NT)
        cp_async16(s0 + i * 16, base + i * 4);
    cp_commit();

    const int2* tr2 = (const int2*)(tree + (size_t)b * EED * 2);
    int2 ed[EPT];
    float acc[EPT];
#pragma unroll
    for (int k = 0; k < EPT; k++) {
        int e = tid + k * NT;
        ed[k]  = (e < EED) ? tr2[e] : make_int2(0, 0);
        acc[k] = 0.f;
    }

    for (int t = 0; t < NSTEP; t++) {
        if (t + 1 < NSTEP) {
            uint32_t dst = (t & 1) ? s0 : s1;
            const float* srcp = base + (size_t)(t + 1) * TCH * NND;
            for (int i = tid; i < WORDS; i += NT)
                cp_async16(dst + i * 16, srcp + i * 4);
            cp_commit();
            cp_wait<1>();
        } else {
            cp_wait<0>();
        }
        __syncthreads();
        const float* cur = (t & 1) ? buf1 : buf0;
#pragma unroll
        for (int k = 0; k < EPT; k++) {
            float a0 = cur[ed[k].x];
            float b0 = cur[ed[k].y];
            float a1 = cur[NND + ed[k].x];
            float b1 = cur[NND + ed[k].y];
            float d0 = a0 - b0, d1 = a1 - b1;
            acc[k] += d0 * d0 + d1 * d1;
        }
        __syncthreads();
    }

    float* sp = g_sum + (size_t)b * EED;
#pragma unroll
    for (int k = 0; k < EPT; k++) {
        int e = tid + k * NT;
        if (e < EED) atomicAdd(sp + e, acc[k]);
    }
}

// ---------------------------------------------------------------------------
// Prologue role: tree-only; runs concurrently with dist (R8 version).
// ---------------------------------------------------------------------------
__device__ void prologue_role(const int* __restrict__ tree, int b) {
    const int tid = threadIdx.x;
    const int wid = tid >> 5;
    const int lid = tid & 31;

    int* par = (int*)dyn_smem;
    int* dep = par + NND;

    __shared__ int hist[MAXD + 1];
    __shared__ int lvlo[MAXD + 2];
    __shared__ int warpsum[16];
    __shared__ int s_maxLvl, s_bad;

    const int2* tr2 = (const int2*)(tree + (size_t)b * EED * 2);

    if (tid == 0) { s_maxLvl = 1; s_bad = 0; par[0] = 0; dep[0] = 0; }
    int2 ed[EPT];
#pragma unroll
    for (int k = 0; k < EPT; k++) {
        int e = tid + k * NT;
        ed[k] = (e < EED) ? tr2[e] : make_int2(0, 0);
        if (e < EED) par[ed[k].y] = ed[k].x;
    }
    __syncthreads();

#pragma unroll 1
    for (int c = 0; c < NCHUNK; c++) {
        int i = c * NT + tid;
        if (i > 0) {
            int B = c * NT;
            int j = par[i], d = 1;
            while (j >= B && j > 0) { j = par[j]; d++; }
            dep[i] = d + dep[j];
        }
        __syncthreads();
    }

    for (int k = tid; k <= MAXD; k += NT) hist[k] = 0;
    __syncthreads();
    int myd[EPT];
#pragma unroll
    for (int k = 0; k < EPT; k++) {
        int e = tid + k * NT;
        if (e < EED) {
            int d = dep[ed[k].y];
            myd[k] = d > MAXD ? MAXD : d;
            atomicAdd(&hist[myd[k]], 1);
        } else myd[k] = 0;
    }
    __syncthreads();

    // 2-barrier block scan over 512 bins
    int binv = 0, incl = 0, bin = 0;
    if (wid < 16) {
        bin  = wid * 32 + lid;
        binv = hist[bin];
        int v = binv;
#pragma unroll
        for (int off = 1; off < 32; off <<= 1) {
            int t = __shfl_up_sync(0xffffffffu, v, off);
            if (lid >= off) v += t;
        }
        if (lid == 31) warpsum[wid] = v;
        incl = v;
    }
    __syncthreads();
    if (wid == 0 && lid < 16) {
        int v = warpsum[lid];
#pragma unroll
        for (int off = 1; off < 16; off <<= 1) {
            int t = __shfl_up_sync(0xffffu, v, off);
            if (lid >= off) v += t;
        }
        warpsum[lid] = v;
    }
    __syncthreads();
    if (wid < 16) {
        incl += wid ? warpsum[wid - 1] : 0;
        lvlo[bin + 1] = incl;
        hist[bin] = incl - binv;
        if (binv > 0)  atomicMax(&s_maxLvl, bin);
        if (binv > 32) atomicMax(&s_bad, bin);
    }
    if (tid == 0) lvlo[0] = 0;
    __syncthreads();

    int2* stp = g_ST + (size_t)b * EEDP;
#pragma unroll
    for (int k = 0; k < EPT; k++) {
        int e = tid + k * NT;
        if (e < EED) {
            int pos = atomicAdd(&hist[myd[k]], 1);
            stp[pos] = ed[k];
        }
    }
    for (int k = tid; k <= MAXD + 1; k += NT) g_lvlo[b][k] = lvlo[k];
    if (tid == 0) g_meta[b] = make_int2(s_maxLvl, s_bad);
}

__global__ void __launch_bounds__(NT, 1)
fused_kernel(const float* __restrict__ emb, const int* __restrict__ tree) {
    if (blockIdx.x < BS * GQ) dist_role(emb, tree, blockIdx.x);
    else                      prologue_role(tree, blockIdx.x - BS * GQ);
}

// ---------------------------------------------------------------------------
// Pass kernel (R8 shape): 16 blocks = (batch, field), 1024 threads.
// Levels with <=32 edges run on warp 0 (syncwarp); big levels full block.
// Field 0 = F (waits for Z, writes F/G); field 1 = G (publishes Z,
// re-zeroes g_sum). Weights from g_sum inline (edge id = t-1).
// smem: S float[NND] | ST int2[EEDP] | W float[EEDP]
// ---------------------------------------------------------------------------
__global__ void __launch_bounds__(NT, 1)
pass_kernel(const float* __restrict__ fin, float* __restrict__ out) {
    const int b     = blockIdx.x >> 1;
    const int which = blockIdx.x & 1;
    const int tid   = threadIdx.x;
    const int wid   = tid >> 5;
    const int lid   = tid & 31;

    char*  smbase = (char*)dyn_smem;
    float* S  = (float*)smbase;
    int2*  ST = (int2*)(smbase + (size_t)NND * 4);
    float* W  = (float*)(smbase + (size_t)NND * 4 + (size_t)EEDP * 8);

    __shared__ int lvlo[MAXD + 2];

    const int2 meta = g_meta[b];
    const int maxLvl = meta.x, bad = meta.y;

    for (int k = tid; k <= maxLvl + 1; k += NT) lvlo[k] = g_lvlo[b][k];

    // load sorted edges + compute weights (edge id = child - 1)
    const int2*  stp = g_ST + (size_t)b * EEDP;
    float*       sp  = g_sum + (size_t)b * EED;
    for (int i = tid; i < EED; i += NT) {
        int2 st = stp[i];
        ST[i] = st;
        W[i]  = __expf(-ZETA * __ldg((const float*)sp + (st.y - 1)));
    }

    // init field
    if (which == 0) {
        const float* fb = fin + (size_t)b * NND;
        for (int i = tid; i < NND; i += NT) S[i] = fb[i];
    } else {
        for (int i = tid; i < NND; i += NT) S[i] = 1.f;
    }
    __syncthreads();

    // F-block signals it is done reading g_sum
    if (which == 0 && tid == 0) {
        __threadfence();
        atomicExch(&g_flagW[b], 1);
    }

    // ---- UP pass: tail (small deep levels) on warp 0 ----
    if (wid == 0) {
#pragma unroll 1
        for (int d = maxLvl; d > bad; --d) {
            int idx = lvlo[d] + lid;
            if (idx < lvlo[d + 1]) {
                int2 st = ST[idx];
                atomicAdd(&S[st.x], W[idx] * S[st.y]);
            }
            __syncwarp();
        }
    }
    __syncthreads();
#pragma unroll 1
    for (int d = bad; d >= 1; --d) {
        int end = lvlo[d + 1];
        for (int idx = lvlo[d] + tid; idx < end; idx += NT) {
            int2 st = ST[idx];
            atomicAdd(&S[st.x], W[idx] * S[st.y]);
        }
        __syncthreads();
    }

    // ---- DOWN pass ----
#pragma unroll 1
    for (int d = 1; d <= bad; ++d) {
        int end = lvlo[d + 1];
        for (int idx = lvlo[d] + tid; idx < end; idx += NT) {
            int2 st = ST[idx];
            float w = W[idx];
            S[st.y] = w * S[st.x] + (1.f - w * w) * S[st.y];
        }
        __syncthreads();
    }
    if (wid == 0) {
#pragma unroll 1
        for (int d = bad + 1; d <= maxLvl; ++d) {
            int idx = lvlo[d] + lid;
            if (idx < lvlo[d + 1]) {
                int2 st = ST[idx];
                float w = W[idx];
                S[st.y] = w * S[st.x] + (1.f - w * w) * S[st.y];
            }
            __syncwarp();
        }
    }
    __syncthreads();

    if (which == 1) {
        // publish Z, then (after F-block released g_sum) re-zero it
        float* zp = g_Z + (size_t)b * NND;
        for (int i = tid; i < NND; i += NT) zp[i] = S[i];
        __threadfence();
        __syncthreads();
        if (tid == 0) {
            atomicExch(&g_flagZ[b], 1);
            while (atomicAdd(&g_flagW[b], 0) == 0) __nanosleep(64);
            atomicExch(&g_flagW[b], 0);        // reset for next replay
        }
        __syncthreads();
        for (int e = tid; e < EED; e += NT) sp[e] = 0.f;
    } else {
        // wait for Z, divide, write output
        if (tid == 0) {
            while (atomicAdd(&g_flagZ[b], 0) == 0) __nanosleep(64);
            __threadfence();
            atomicExch(&g_flagZ[b], 0);        // reset for next replay
        }
        __syncthreads();
        const float* zp = g_Z + (size_t)b * NND;
        float* ob = out + (size_t)b * NND;
        for (int i = tid; i < NND; i += NT) ob[i] = S[i] / zp[i];
    }
}

// ---------------------------------------------------------------------------
extern "C" void kernel_launch(void* const* d_in, const int* in_sizes, int n_in,
                              void* d_out, int out_size) {
    const float* f    = (const float*)d_in[0];   // feature_in [8,1,96,96]
    const float* emb  = (const float*)d_in[1];   // embed_in   [8,256,96,96]
    const int*   tree = (const int*)d_in[2];     // tree       [8,9215,2]
    float*       out  = (float*)d_out;           // [8,1,96,96]

    size_t smem1 = 2 * (size_t)TCH * NND * sizeof(float);   // 147456 B
    cudaFuncSetAttribute(fused_kernel,
                         cudaFuncAttributeMaxDynamicSharedMemorySize,
                         (int)smem1);
    fused_kernel<<<GRID1, NT, smem1>>>(emb, tree);

    size_t smem2 = (size_t)NND * 4 + (size_t)EEDP * 8 + (size_t)EEDP * 4;
    cudaFuncSetAttribute(pass_kernel,
                         cudaFuncAttributeMaxDynamicSharedMemorySize,
                         (int)smem2);
    pass_kernel<<<2 * BS, NT, smem2>>>(f, out);
}

// round 13
// speedup vs baseline: 1.1922x; 1.0357x over previous
#include <cuda_runtime.h>
#include <stdint.h>
#include <math.h>

#define BS   8
#define CCH  256
#define NND  9216     // H*W
#define EED  9215     // N-1 edges
#define EEDP 9216     // padded
#define ZETA 0.01f

#define CPB  16               // channels per dist block
#define GQ   (CCH/CPB)        // 16 groups per batch
#define TCH  2                // channels per tile step
#define NSTEP (CPB/TCH)       // 8 tile steps
#define MAXD 511
#define NT   1024
#define EPT  9                // ceil(EED/NT)
#define NCHUNK (NND/NT)       // 9
#define GRID (BS*GQ + 2*BS)   // 128 dist + 16 pass = 144 (<=148, co-resident)

// static device scratch (zero-init at load; counters/flags self-resetting)
__device__ float g_sum[(size_t)BS * EED];        // per-edge squared dist
__device__ float g_Z[(size_t)BS * NND];          // G field (denominator)
__device__ int   g_done[BS];                     // dist blocks finished
__device__ int   g_flagW[BS];                    // F-block done reading g_sum
__device__ int   g_flagZ[BS];                    // Z published

extern __shared__ float dyn_smem[];

__device__ __forceinline__ void cp_async16(uint32_t saddr, const void* gptr) {
    asm volatile("cp.async.cg.shared.global [%0], [%1], 16;\n"
                 :: "r"(saddr), "l"(gptr));
}
__device__ __forceinline__ void cp_commit() {
    asm volatile("cp.async.commit_group;\n");
}
template <int N>
__device__ __forceinline__ void cp_wait() {
    asm volatile("cp.async.wait_group %0;\n" :: "n"(N));
}

// ---------------------------------------------------------------------------
// Dist role: blocks 0..127. One block per (batch, 16-channel group);
// double-buffered cp.async tiles; partials REDG'd into g_sum; signals done.
// ---------------------------------------------------------------------------
__device__ void dist_role(const float* __restrict__ emb,
                          const int*   __restrict__ tree, int id) {
    float* buf0 = dyn_smem;
    float* buf1 = dyn_smem + TCH * NND;
    const int b   = id / GQ;
    const int g   = id % GQ;
    const int tid = threadIdx.x;

    const float* base = emb + ((size_t)b * CCH + (size_t)g * CPB) * NND;
    uint32_t s0 = (uint32_t)__cvta_generic_to_shared(buf0);
    uint32_t s1 = (uint32_t)__cvta_generic_to_shared(buf1);
    const int WORDS = TCH * NND / 4;

    for (int i = tid; i < WORDS; i += NT)
        cp_async16(s0 + i * 16, base + i * 4);
    cp_commit();

    const int2* tr2 = (const int2*)(tree + (size_t)b * EED * 2);
    int2 ed[EPT];
    float acc[EPT];
#pragma unroll
    for (int k = 0; k < EPT; k++) {
        int e = tid + k * NT;
        ed[k]  = (e < EED) ? tr2[e] : make_int2(0, 0);
        acc[k] = 0.f;
    }

    for (int t = 0; t < NSTEP; t++) {
        if (t + 1 < NSTEP) {
            uint32_t dst = (t & 1) ? s0 : s1;
            const float* srcp = base + (size_t)(t + 1) * TCH * NND;
            for (int i = tid; i < WORDS; i += NT)
                cp_async16(dst + i * 16, srcp + i * 4);
            cp_commit();
            cp_wait<1>();
        } else {
            cp_wait<0>();
        }
        __syncthreads();
        const float* cur = (t & 1) ? buf1 : buf0;
#pragma unroll
        for (int k = 0; k < EPT; k++) {
            float a0 = cur[ed[k].x];
            float b0 = cur[ed[k].y];
            float a1 = cur[NND + ed[k].x];
            float b1 = cur[NND + ed[k].y];
            float d0 = a0 - b0, d1 = a1 - b1;
            acc[k] += d0 * d0 + d1 * d1;
        }
        __syncthreads();
    }

    float* sp = g_sum + (size_t)b * EED;
#pragma unroll
    for (int k = 0; k < EPT; k++) {
        int e = tid + k * NT;
        if (e < EED) atomicAdd(sp + e, acc[k]);
    }

    __threadfence();
    __syncthreads();
    if (tid == 0) atomicAdd(&g_done[b], 1);
}

// ---------------------------------------------------------------------------
// Pass role: blocks 128..143 = (batch, field). Does its own prologue in smem
// (overlapped with dist), spins on g_done[b]==GQ, fills W, runs the proven
// level-parallel passes. Field 0 = F (writes F/G), field 1 = G (publishes Z,
// zeroes g_sum, resets g_done).
// smem: S f[NND] | ST int2[EEDP] | W f[EEDP]; prologue: par in S, dep in W.
// ---------------------------------------------------------------------------
__device__ void pass_role(const float* __restrict__ fin,
                          const int*   __restrict__ tree,
                          float*       __restrict__ out,
                          int b, int which) {
    const int tid = threadIdx.x;
    const int wid = tid >> 5;
    const int lid = tid & 31;

    char*  smbase = (char*)dyn_smem;
    float* S  = (float*)smbase;
    int2*  ST = (int2*)(smbase + (size_t)NND * 4);
    float* W  = (float*)(smbase + (size_t)NND * 4 + (size_t)EEDP * 8);
    int*   par = (int*)smbase;                                   // prologue
    int*   dep = (int*)(smbase + (size_t)NND * 4 + (size_t)EEDP * 8);

    __shared__ int hist[MAXD + 1];
    __shared__ int lvlo[MAXD + 2];
    __shared__ int warpsum[16];
    __shared__ int s_maxLvl, s_bad;

    const int2* tr2 = (const int2*)(tree + (size_t)b * EED * 2);

    // ================= prologue (tree-only, overlapped with dist) ==========
    if (tid == 0) { s_maxLvl = 1; s_bad = 0; par[0] = 0; dep[0] = 0; }
    int2 ed[EPT];
#pragma unroll
    for (int k = 0; k < EPT; k++) {
        int e = tid + k * NT;
        ed[k] = (e < EED) ? tr2[e] : make_int2(0, 0);
        if (e < EED) par[ed[k].y] = ed[k].x;
    }
    __syncthreads();

    // depth: chunked walk (parent index < child index)
#pragma unroll 1
    for (int c = 0; c < NCHUNK; c++) {
        int i = c * NT + tid;
        if (i > 0) {
            int B = c * NT;
            int j = par[i], d = 1;
            while (j >= B && j > 0) { j = par[j]; d++; }
            dep[i] = d + dep[j];
        }
        __syncthreads();
    }

    // histogram of child depths
    for (int k = tid; k <= MAXD; k += NT) hist[k] = 0;
    __syncthreads();
    int myd[EPT];
#pragma unroll
    for (int k = 0; k < EPT; k++) {
        int e = tid + k * NT;
        if (e < EED) {
            int d = dep[ed[k].y];
            myd[k] = d > MAXD ? MAXD : d;
            atomicAdd(&hist[myd[k]], 1);
        } else myd[k] = 0;
    }
    __syncthreads();

    // 2-barrier block scan over 512 bins
    {
        int binv = 0, incl = 0, bin = 0;
        if (wid < 16) {
            bin  = wid * 32 + lid;
            binv = hist[bin];
            int v = binv;
#pragma unroll
            for (int off = 1; off < 32; off <<= 1) {
                int t = __shfl_up_sync(0xffffffffu, v, off);
                if (lid >= off) v += t;
            }
            if (lid == 31) warpsum[wid] = v;
            incl = v;
        }
        __syncthreads();
        if (wid == 0 && lid < 16) {
            int v = warpsum[lid];
#pragma unroll
            for (int off = 1; off < 16; off <<= 1) {
                int t = __shfl_up_sync(0xffffu, v, off);
                if (lid >= off) v += t;
            }
            warpsum[lid] = v;
        }
        __syncthreads();
        if (wid < 16) {
            incl += wid ? warpsum[wid - 1] : 0;
            lvlo[bin + 1] = incl;
            hist[bin] = incl - binv;          // exclusive cursor
            if (binv > 0)  atomicMax(&s_maxLvl, bin);
            if (binv > 32) atomicMax(&s_bad, bin);
        }
        if (tid == 0) lvlo[0] = 0;
        __syncthreads();
    }

    // scatter (s,t) into level-sorted smem ST
#pragma unroll
    for (int k = 0; k < EPT; k++) {
        int e = tid + k * NT;
        if (e < EED) {
            int pos = atomicAdd(&hist[myd[k]], 1);
            ST[pos] = ed[k];
        }
    }
    __syncthreads();   // dep (in W region) dead after this

    // init field S (overwrites par region)
    if (which == 0) {
        const float* fb = fin + (size_t)b * NND;
        for (int i = tid; i < NND; i += NT) S[i] = fb[i];
    } else {
        for (int i = tid; i < NND; i += NT) S[i] = 1.f;
    }

    // ================= wait for dist, then weights ==========================
    if (tid == 0) {
        while (atomicAdd(&g_done[b], 0) < GQ) __nanosleep(64);
        __threadfence();
    }
    __syncthreads();

    const float* sp = g_sum + (size_t)b * EED;
    for (int i = tid; i < EED; i += NT) {
        int t = ST[i].y;
        W[i] = __expf(-ZETA * __ldcg(sp + (t - 1)));
    }
    __syncthreads();

    // F-block done reading g_sum
    if (which == 0 && tid == 0) {
        __threadfence();
        atomicExch(&g_flagW[b], 1);
    }

    const int maxLvl = s_maxLvl;
    const int bad    = s_bad;

    // ================= UP pass ==============================================
    if (wid == 0) {
#pragma unroll 1
        for (int d = maxLvl; d > bad; --d) {
            int idx = lvlo[d] + lid;
            if (idx < lvlo[d + 1]) {
                int2 st = ST[idx];
                atomicAdd(&S[st.x], W[idx] * S[st.y]);
            }
            __syncwarp();
        }
    }
    __syncthreads();
#pragma unroll 1
    for (int d = bad; d >= 1; --d) {
        int end = lvlo[d + 1];
        for (int idx = lvlo[d] + tid; idx < end; idx += NT) {
            int2 st = ST[idx];
            atomicAdd(&S[st.x], W[idx] * S[st.y]);
        }
        __syncthreads();
    }

    // ================= DOWN pass ============================================
#pragma unroll 1
    for (int d = 1; d <= bad; ++d) {
        int end = lvlo[d + 1];
        for (int idx = lvlo[d] + tid; idx < end; idx += NT) {
            int2 st = ST[idx];
            float w = W[idx];
            S[st.y] = w * S[st.x] + (1.f - w * w) * S[st.y];
        }
        __syncthreads();
    }
    if (wid == 0) {
#pragma unroll 1
        for (int d = bad + 1; d <= maxLvl; ++d) {
            int idx = lvlo[d] + lid;
            if (idx < lvlo[d + 1]) {
                int2 st = ST[idx];
                float w = W[idx];
                S[st.y] = w * S[st.x] + (1.f - w * w) * S[st.y];
            }
            __syncwarp();
        }
    }
    __syncthreads();

    // ================= exchange + output + replay hygiene ===================
    if (which == 1) {
        float* zp = g_Z + (size_t)b * NND;
        for (int i = tid; i < NND; i += NT) zp[i] = S[i];
        __threadfence();
        __syncthreads();
        if (tid == 0) {
            atomicExch(&g_flagZ[b], 1);
            while (atomicAdd(&g_flagW[b], 0) == 0) __nanosleep(64);
            atomicExch(&g_flagW[b], 0);        // reset for next replay
        }
        __syncthreads();
        float* spw = g_sum + (size_t)b * EED;
        for (int e = tid; e < EED; e += NT) spw[e] = 0.f;
        if (tid == 0) atomicExch(&g_done[b], 0);   // reset for next replay
    } else {
        if (tid == 0) {
            while (atomicAdd(&g_flagZ[b], 0) == 0) __nanosleep(64);
            __threadfence();
            atomicExch(&g_flagZ[b], 0);        // reset for next replay
        }
        __syncthreads();
        const float* zp = g_Z + (size_t)b * NND;
        float* ob = out + (size_t)b * NND;
        for (int i = tid; i < NND; i += NT) ob[i] = S[i] / __ldcg(zp + i);
    }
}

// ---------------------------------------------------------------------------
__global__ void __launch_bounds__(NT, 1)
mega_kernel(const float* __restrict__ fin,
            const float* __restrict__ emb,
            const int*   __restrict__ tree,
            float*       __restrict__ out) {
    if (blockIdx.x < BS * GQ) {
        dist_role(emb, tree, blockIdx.x);
    } else {
        int r = blockIdx.x - BS * GQ;
        pass_role(fin, tree, out, r >> 1, r & 1);
    }
}

// ---------------------------------------------------------------------------
extern "C" void kernel_launch(void* const* d_in, const int* in_sizes, int n_in,
                              void* d_out, int out_size) {
    const float* f    = (const float*)d_in[0];   // feature_in [8,1,96,96]
    const float* emb  = (const float*)d_in[1];   // embed_in   [8,256,96,96]
    const int*   tree = (const int*)d_in[2];     // tree       [8,9215,2]
    float*       out  = (float*)d_out;           // [8,1,96,96]

    size_t smem = (size_t)NND * 4 + (size_t)EEDP * 8 + (size_t)EEDP * 4; // 147456
    cudaFuncSetAttribute(mega_kernel,
                         cudaFuncAttributeMaxDynamicSharedMemorySize,
                         (int)smem);
    mega_kernel<<<GRID, NT, smem>>>(f, emb, tree, out);
}

// round 14
// speedup vs baseline: 1.1981x; 1.0050x over previous
#include <cuda_runtime.h>
#include <stdint.h>
#include <math.h>

#define BS   8
#define CCH  256
#define NND  9216     // H*W
#define EED  9215     // N-1 edges
#define EEDP 9216     // padded
#define ZETA 0.01f

#define CPB  16               // channels per dist block
#define GQ   (CCH/CPB)        // 16 groups per batch
#define TCH  2                // channels per tile step
#define NSTEP (CPB/TCH)       // 8 tile steps
#define MAXD 511
#define NT   1024
#define EPT  9                // ceil(EED/NT)
#define NCHUNK (NND/NT)       // 9
#define GRID (BS*GQ + 2*BS)   // 128 dist + 16 pass = 144 (<=148, co-resident)

// static device scratch (zero-init at load; counters/flags self-resetting)
__device__ float g_sum[(size_t)BS * EED];        // per-edge squared dist
__device__ float g_Z[(size_t)BS * NND];          // G field (denominator)
__device__ int   g_done[BS];                     // dist blocks finished
__device__ int   g_flagW[BS];                    // F-block done reading g_sum
__device__ int   g_flagZ[BS];                    // Z published

extern __shared__ float dyn_smem[];

__device__ __forceinline__ void cp_async16(uint32_t saddr, const void* gptr) {
    asm volatile("cp.async.cg.shared.global [%0], [%1], 16;\n"
                 :: "r"(saddr), "l"(gptr));
}
__device__ __forceinline__ void cp_commit() {
    asm volatile("cp.async.commit_group;\n");
}
template <int N>
__device__ __forceinline__ void cp_wait() {
    asm volatile("cp.async.wait_group %0;\n" :: "n"(N));
}

// ---------------------------------------------------------------------------
// Dist role: blocks 0..127 (unchanged from R13).
// ---------------------------------------------------------------------------
__device__ void dist_role(const float* __restrict__ emb,
                          const int*   __restrict__ tree, int id) {
    float* buf0 = dyn_smem;
    float* buf1 = dyn_smem + TCH * NND;
    const int b   = id / GQ;
    const int g   = id % GQ;
    const int tid = threadIdx.x;

    const float* base = emb + ((size_t)b * CCH + (size_t)g * CPB) * NND;
    uint32_t s0 = (uint32_t)__cvta_generic_to_shared(buf0);
    uint32_t s1 = (uint32_t)__cvta_generic_to_shared(buf1);
    const int WORDS = TCH * NND / 4;

    for (int i = tid; i < WORDS; i += NT)
        cp_async16(s0 + i * 16, base + i * 4);
    cp_commit();

    const int2* tr2 = (const int2*)(tree + (size_t)b * EED * 2);
    int2 ed[EPT];
    float acc[EPT];
#pragma unroll
    for (int k = 0; k < EPT; k++) {
        int e = tid + k * NT;
        ed[k]  = (e < EED) ? tr2[e] : make_int2(0, 0);
        acc[k] = 0.f;
    }

    for (int t = 0; t < NSTEP; t++) {
        if (t + 1 < NSTEP) {
            uint32_t dst = (t & 1) ? s0 : s1;
            const float* srcp = base + (size_t)(t + 1) * TCH * NND;
            for (int i = tid; i < WORDS; i += NT)
                cp_async16(dst + i * 16, srcp + i * 4);
            cp_commit();
            cp_wait<1>();
        } else {
            cp_wait<0>();
        }
        __syncthreads();
        const float* cur = (t & 1) ? buf1 : buf0;
#pragma unroll
        for (int k = 0; k < EPT; k++) {
            float a0 = cur[ed[k].x];
            float b0 = cur[ed[k].y];
            float a1 = cur[NND + ed[k].x];
            float b1 = cur[NND + ed[k].y];
            float d0 = a0 - b0, d1 = a1 - b1;
            acc[k] += d0 * d0 + d1 * d1;
        }
        __syncthreads();
    }

    float* sp = g_sum + (size_t)b * EED;
#pragma unroll
    for (int k = 0; k < EPT; k++) {
        int e = tid + k * NT;
        if (e < EED) atomicAdd(sp + e, acc[k]);
    }

    __threadfence();
    __syncthreads();
    if (tid == 0) atomicAdd(&g_done[b], 1);
}

// ---------------------------------------------------------------------------
// Pass role: blocks 128..143 = (batch, field). Own prologue in smem
// (overlapped with dist), spin on g_done, W-fill, level passes with
// cross-barrier prefetch of read-only ST/W (and S[child] in the down pass).
// smem: S f[NND] | ST int2[EEDP] | W f[EEDP]; prologue: par in S, dep in W.
// ---------------------------------------------------------------------------
__device__ void pass_role(const float* __restrict__ fin,
                          const int*   __restrict__ tree,
                          float*       __restrict__ out,
                          int b, int which) {
    const int tid = threadIdx.x;
    const int wid = tid >> 5;
    const int lid = tid & 31;

    char*  smbase = (char*)dyn_smem;
    float* S  = (float*)smbase;
    int2*  ST = (int2*)(smbase + (size_t)NND * 4);
    float* W  = (float*)(smbase + (size_t)NND * 4 + (size_t)EEDP * 8);
    int*   par = (int*)smbase;                                   // prologue
    int*   dep = (int*)(smbase + (size_t)NND * 4 + (size_t)EEDP * 8);

    __shared__ int hist[MAXD + 1];
    __shared__ int lvlo[MAXD + 2];
    __shared__ int warpsum[16];
    __shared__ int s_maxLvl, s_bad;

    const int2* tr2 = (const int2*)(tree + (size_t)b * EED * 2);

    // ================= prologue (tree-only, overlapped with dist) ==========
    if (tid == 0) { s_maxLvl = 1; s_bad = 0; par[0] = 0; dep[0] = 0; }
    int2 ed[EPT];
#pragma unroll
    for (int k = 0; k < EPT; k++) {
        int e = tid + k * NT;
        ed[k] = (e < EED) ? tr2[e] : make_int2(0, 0);
        if (e < EED) par[ed[k].y] = ed[k].x;
    }
    __syncthreads();

#pragma unroll 1
    for (int c = 0; c < NCHUNK; c++) {
        int i = c * NT + tid;
        if (i > 0) {
            int B = c * NT;
            int j = par[i], d = 1;
            while (j >= B && j > 0) { j = par[j]; d++; }
            dep[i] = d + dep[j];
        }
        __syncthreads();
    }

    for (int k = tid; k <= MAXD; k += NT) hist[k] = 0;
    __syncthreads();
    int myd[EPT];
#pragma unroll
    for (int k = 0; k < EPT; k++) {
        int e = tid + k * NT;
        if (e < EED) {
            int d = dep[ed[k].y];
            myd[k] = d > MAXD ? MAXD : d;
            atomicAdd(&hist[myd[k]], 1);
        } else myd[k] = 0;
    }
    __syncthreads();

    // 2-barrier block scan over 512 bins
    {
        int binv = 0, incl = 0, bin = 0;
        if (wid < 16) {
            bin  = wid * 32 + lid;
            binv = hist[bin];
            int v = binv;
#pragma unroll
            for (int off = 1; off < 32; off <<= 1) {
                int t = __shfl_up_sync(0xffffffffu, v, off);
                if (lid >= off) v += t;
            }
            if (lid == 31) warpsum[wid] = v;
            incl = v;
        }
        __syncthreads();
        if (wid == 0 && lid < 16) {
            int v = warpsum[lid];
#pragma unroll
            for (int off = 1; off < 16; off <<= 1) {
                int t = __shfl_up_sync(0xffffu, v, off);
                if (lid >= off) v += t;
            }
            warpsum[lid] = v;
        }
        __syncthreads();
        if (wid < 16) {
            incl += wid ? warpsum[wid - 1] : 0;
            lvlo[bin + 1] = incl;
            hist[bin] = incl - binv;          // exclusive cursor
            if (binv > 0)  atomicMax(&s_maxLvl, bin);
            if (binv > 32) atomicMax(&s_bad, bin);
        }
        if (tid == 0) lvlo[0] = 0;
        __syncthreads();
    }

    // scatter (s,t) into level-sorted smem ST
#pragma unroll
    for (int k = 0; k < EPT; k++) {
        int e = tid + k * NT;
        if (e < EED) {
            int pos = atomicAdd(&hist[myd[k]], 1);
            ST[pos] = ed[k];
        }
    }
    __syncthreads();   // dep (in W region) dead after this

    // init field S (overwrites par region)
    if (which == 0) {
        const float* fb = fin + (size_t)b * NND;
        for (int i = tid; i < NND; i += NT) S[i] = fb[i];
    } else {
        for (int i = tid; i < NND; i += NT) S[i] = 1.f;
    }

    // ================= wait for dist, then weights ==========================
    if (tid == 0) {
        while (atomicAdd(&g_done[b], 0) < GQ) __nanosleep(64);
        __threadfence();
    }
    __syncthreads();

    const float* sp = g_sum + (size_t)b * EED;
    for (int i = tid; i < EED; i += NT) {
        int t = ST[i].y;
        W[i] = __expf(-ZETA * __ldcg(sp + (t - 1)));
    }
    __syncthreads();

    if (which == 0 && tid == 0) {
        __threadfence();
        atomicExch(&g_flagW[b], 1);
    }

    const int maxLvl = s_maxLvl;
    const int bad    = s_bad;

    // ================= UP pass ==============================================
    // tail (deep, <=32-edge levels) on warp 0, with ST/W prefetch
    if (wid == 0 && maxLvl > bad) {
        int idx = lvlo[maxLvl] + lid;
        bool act = idx < lvlo[maxLvl + 1];
        int2 stc = make_int2(0, 0); float wc = 0.f;
        if (act) { stc = ST[idx]; wc = W[idx]; }
#pragma unroll 1
        for (int d = maxLvl; d > bad; --d) {
            bool actn = false; int2 stn = make_int2(0, 0); float wn = 0.f;
            if (d - 1 > bad) {
                int nidx = lvlo[d - 1] + lid;
                actn = nidx < lvlo[d];
                if (actn) { stn = ST[nidx]; wn = W[nidx]; }
            }
            if (act) atomicAdd(&S[stc.x], wc * S[stc.y]);
            __syncwarp();
            act = actn; stc = stn; wc = wn;
        }
    }
    __syncthreads();
    // big levels, with ST/W prefetch across the barrier
    if (bad >= 1) {
        int beg = lvlo[bad], end = lvlo[bad + 1];
        bool act = beg + tid < end;
        int2 stc = make_int2(0, 0); float wc = 0.f;
        if (act) { stc = ST[beg + tid]; wc = W[beg + tid]; }
#pragma unroll 1
        for (int d = bad; d >= 1; --d) {
            int nbeg = 0, nend = 0; bool actn = false;
            int2 stn = make_int2(0, 0); float wn = 0.f;
            if (d > 1) {
                nbeg = lvlo[d - 1]; nend = lvlo[d];
                actn = nbeg + tid < nend;
                if (actn) { stn = ST[nbeg + tid]; wn = W[nbeg + tid]; }
            }
            if (act) atomicAdd(&S[stc.x], wc * S[stc.y]);
            for (int idx2 = beg + tid + NT; idx2 < end; idx2 += NT) {
                int2 st = ST[idx2];
                atomicAdd(&S[st.x], W[idx2] * S[st.y]);
            }
            __syncthreads();
            beg = nbeg; end = nend; act = actn; stc = stn; wc = wn;
        }
    }

    // ================= DOWN pass ============================================
    // big levels 1..bad, prefetching ST/W and S[child] (child written only
    // at its own level, so a depth-(d+1) read during level d is safe)
    if (bad >= 1) {
        int beg = lvlo[1], end = lvlo[2];
        bool act = beg + tid < end;
        int2 stc = make_int2(0, 0); float wc = 0.f, syc = 0.f;
        if (act) { stc = ST[beg + tid]; wc = W[beg + tid]; syc = S[stc.y]; }
#pragma unroll 1
        for (int d = 1; d <= bad; ++d) {
            int nbeg = 0, nend = 0; bool actn = false;
            int2 stn = make_int2(0, 0); float wn = 0.f, syn = 0.f;
            if (d < bad) {
                nbeg = lvlo[d + 1]; nend = lvlo[d + 2];
                actn = nbeg + tid < nend;
                if (actn) { stn = ST[nbeg + tid]; wn = W[nbeg + tid];
                            syn = S[stn.y]; }
            }
            if (act) S[stc.y] = wc * S[stc.x] + (1.f - wc * wc) * syc;
            for (int idx2 = beg + tid + NT; idx2 < end; idx2 += NT) {
                int2 st = ST[idx2];
                float w = W[idx2];
                S[st.y] = w * S[st.x] + (1.f - w * w) * S[st.y];
            }
            __syncthreads();
            beg = nbeg; end = nend; act = actn;
            stc = stn; wc = wn; syc = syn;
        }
    }
    // tail on warp 0, same prefetch incl. S[child]
    if (wid == 0 && bad + 1 <= maxLvl) {
        int idx = lvlo[bad + 1] + lid;
        bool act = idx < lvlo[bad + 2];
        int2 stc = make_int2(0, 0); float wc = 0.f, syc = 0.f;
        if (act) { stc = ST[idx]; wc = W[idx]; syc = S[stc.y]; }
#pragma unroll 1
        for (int d = bad + 1; d <= maxLvl; ++d) {
            bool actn = false; int2 stn = make_int2(0, 0);
            float wn = 0.f, syn = 0.f;
            if (d + 1 <= maxLvl) {
                int nidx = lvlo[d + 1] + lid;
                actn = nidx < lvlo[d + 2];
                if (actn) { stn = ST[nidx]; wn = W[nidx]; syn = S[stn.y]; }
            }
            if (act) S[stc.y] = wc * S[stc.x] + (1.f - wc * wc) * syc;
            __syncwarp();
            act = actn; stc = stn; wc = wn; syc = syn;
        }
    }
    __syncthreads();

    // ================= exchange + output + replay hygiene ===================
    if (which == 1) {
        float* zp = g_Z + (size_t)b * NND;
        for (int i = tid; i < NND; i += NT) zp[i] = S[i];
        __threadfence();
        __syncthreads();
        if (tid == 0) {
            atomicExch(&g_flagZ[b], 1);
            while (atomicAdd(&g_flagW[b], 0) == 0) __nanosleep(64);
            atomicExch(&g_flagW[b], 0);        // reset for next replay
        }
        __syncthreads();
        float* spw = g_sum + (size_t)b * EED;
        for (int e = tid; e < EED; e += NT) spw[e] = 0.f;
        if (tid == 0) atomicExch(&g_done[b], 0);   // reset for next replay
    } else {
        if (tid == 0) {
            while (atomicAdd(&g_flagZ[b], 0) == 0) __nanosleep(64);
            __threadfence();
            atomicExch(&g_flagZ[b], 0);        // reset for next replay
        }
        __syncthreads();
        const float* zp = g_Z + (size_t)b * NND;
        float* ob = out + (size_t)b * NND;
        for (int i = tid; i < NND; i += NT) ob[i] = S[i] / __ldcg(zp + i);
    }
}

// ---------------------------------------------------------------------------
__global__ void __launch_bounds__(NT, 1)
mega_kernel(const float* __restrict__ fin,
            const float* __restrict__ emb,
            const int*   __restrict__ tree,
            float*       __restrict__ out) {
    if (blockIdx.x < BS * GQ) {
        dist_role(emb, tree, blockIdx.x);
    } else {
        int r = blockIdx.x - BS * GQ;
        pass_role(fin, tree, out, r >> 1, r & 1);
    }
}

// ---------------------------------------------------------------------------
extern "C" void kernel_launch(void* const* d_in, const int* in_sizes, int n_in,
                              void* d_out, int out_size) {
    const float* f    = (const float*)d_in[0];   // feature_in [8,1,96,96]
    const float* emb  = (const float*)d_in[1];   // embed_in   [8,256,96,96]
    const int*   tree = (const int*)d_in[2];     // tree       [8,9215,2]
    float*       out  = (float*)d_out;           // [8,1,96,96]

    size_t smem = (size_t)NND * 4 + (size_t)EEDP * 8 + (size_t)EEDP * 4; // 147456
    cudaFuncSetAttribute(mega_kernel,
                         cudaFuncAttributeMaxDynamicSharedMemorySize,
                         (int)smem);
    mega_kernel<<<GRID, NT, smem>>>(f, emb, tree, out);
}